// round 14
// baseline (speedup 1.0000x reference)
#include <cuda_runtime.h>
#include <math.h>

#define MDIM  2048
#define NHEAD 32
#define HDIM  64
#define BATCH 16
#define SEQT  256
#define SWIN  512
#define MROWS (BATCH*SEQT)          /* 4096 */
#define WN    (MDIM*MDIM)           /* 4194304 */
#define XN    (MROWS*MDIM)          /* 8388608 */
#define KVN   (BATCH*NHEAD*SWIN*HDIM)   /* 16777216 */
#define QN    (BATCH*NHEAD*SEQT*HDIM)   /*  8388608 */

/* ---------------- scratch (static device arrays; no cudaMalloc) ---------- */
__device__ char           g_x1[XN],  g_x2[XN];             /* X int8 chunks  */
__device__ char           g_w1[4u*WN], g_w2[4u*WN];        /* W int8 chunks  */
__device__ char           g_a1[XN],  g_a2[XN];             /* attn-out int8  */
__device__ float          g_sx[MROWS], g_sw[4*MDIM], g_sa[MROWS];
__device__ float          g_attn[(size_t)MROWS*MDIM];      /* attn out fp32  */
__device__ unsigned short g_qhi[QN], g_qlo[QN];            /* rope'd Q/8     */
__device__ unsigned short g_khi[KVN], g_klo[KVN];          /* K window bf16  */
__device__ unsigned short g_vhi[KVN], g_vlo[KVN];          /* V window bf16  */
__device__ float          g_cos[SEQT*32], g_sin[SEQT*32];

/* ---------------- bf16 helpers (bit-level, rn-even) ----------------------- */
__device__ __forceinline__ unsigned short f2bf(float x) {
    unsigned u = __float_as_uint(x);
    u = u + 0x7fffu + ((u >> 16) & 1u);
    return (unsigned short)(u >> 16);
}
__device__ __forceinline__ unsigned pack2(float x, float y) {
    return (unsigned)f2bf(x) | ((unsigned)f2bf(y) << 16);
}
__device__ __forceinline__ unsigned pack2lo(float x, float y, unsigned hi) {
    float lx = x - __uint_as_float((hi & 0xffffu) << 16);
    float ly = y - __uint_as_float((hi & 0xffff0000u));
    return (unsigned)f2bf(lx) | ((unsigned)f2bf(ly) << 16);
}

__device__ __forceinline__ unsigned s2u(const void* p) {
    unsigned a;
    asm("{ .reg .u64 t; cvta.to.shared.u64 t, %1; cvt.u32.u64 %0, t; }"
        : "=r"(a) : "l"(p));
    return a;
}

/* ---------------- mma.sync / ldmatrix / cp.async (baseline PTX) ----------- */
__device__ __forceinline__ void ldmx4(unsigned* r, unsigned a) {
    asm volatile("ldmatrix.sync.aligned.m8n8.x4.shared.b16 {%0,%1,%2,%3}, [%4];"
                 : "=r"(r[0]), "=r"(r[1]), "=r"(r[2]), "=r"(r[3]) : "r"(a));
}
__device__ __forceinline__ void ldmx4t(unsigned* r, unsigned a) {
    asm volatile("ldmatrix.sync.aligned.m8n8.x4.trans.shared.b16 {%0,%1,%2,%3}, [%4];"
                 : "=r"(r[0]), "=r"(r[1]), "=r"(r[2]), "=r"(r[3]) : "r"(a));
}
__device__ __forceinline__ void mma_bf16(float* c, const unsigned* a,
                                         unsigned b0, unsigned b1) {
    asm volatile("mma.sync.aligned.m16n8k16.row.col.f32.bf16.bf16.f32 "
                 "{%0,%1,%2,%3}, {%4,%5,%6,%7}, {%8,%9}, {%0,%1,%2,%3};"
                 : "+f"(c[0]), "+f"(c[1]), "+f"(c[2]), "+f"(c[3])
                 : "r"(a[0]), "r"(a[1]), "r"(a[2]), "r"(a[3]), "r"(b0), "r"(b1));
}
__device__ __forceinline__ void mma_s8(int* c, const unsigned* a,
                                       unsigned b0, unsigned b1) {
    asm volatile("mma.sync.aligned.m16n8k32.row.col.s32.s8.s8.s32 "
                 "{%0,%1,%2,%3}, {%4,%5,%6,%7}, {%8,%9}, {%0,%1,%2,%3};"
                 : "+r"(c[0]), "+r"(c[1]), "+r"(c[2]), "+r"(c[3])
                 : "r"(a[0]), "r"(a[1]), "r"(a[2]), "r"(a[3]), "r"(b0), "r"(b1));
}
__device__ __forceinline__ void cpa16(unsigned dst, const void* src) {
    asm volatile("cp.async.cg.shared.global [%0], [%1], 16;"
                 :: "r"(dst), "l"(src));
}
__device__ __forceinline__ void cp_commit() {
    asm volatile("cp.async.commit_group;" ::: "memory");
}
__device__ __forceinline__ void cp_wait2() {
    asm volatile("cp.async.wait_group 2;" ::: "memory");
}
__device__ __forceinline__ void cp_wait1() {
    asm volatile("cp.async.wait_group 1;" ::: "memory");
}

/* ---------------- RoPE table (fp64 for large-angle accuracy) -------------- */
__global__ void rope_table_kernel(const int* __restrict__ pos_offset) {
    int idx = blockIdx.x * blockDim.x + threadIdx.x;
    if (idx >= SEQT * 32) return;
    int t = idx >> 5, p = idx & 31;
    double inv = exp(-((double)(2 * p) / 64.0) * log(10000.0));
    double ang = (double)(*pos_offset + t) * inv;
    g_cos[idx] = (float)cos(ang);
    g_sin[idx] = (float)sin(ang);
}

/* ---------------- per-row int8 quantization (Ozaki 2-chunk) ---------------
   x = s*(A1/127 + A2/(127*254)) + eps,  |eps| <= s/(2*127*254)              */
__global__ void quantize_kernel(const float* __restrict__ src,
                                char* __restrict__ d1, char* __restrict__ d2,
                                float* __restrict__ sc) {
    __shared__ float red[8];
    __shared__ float m1s;
    int row = blockIdx.x, tid = threadIdx.x;
    const float* rp = src + (size_t)row * MDIM + tid * 8;
    float4 v0 = *(const float4*)rp;
    float4 v1 = *(const float4*)(rp + 4);
    float vals[8] = {v0.x, v0.y, v0.z, v0.w, v1.x, v1.y, v1.z, v1.w};
    float am = 0.f;
#pragma unroll
    for (int i = 0; i < 8; i++) am = fmaxf(am, fabsf(vals[i]));
#pragma unroll
    for (int o = 16; o; o >>= 1) am = fmaxf(am, __shfl_xor_sync(0xffffffffu, am, o));
    if ((tid & 31) == 0) red[tid >> 5] = am;
    __syncthreads();
    if (tid == 0) {
        float s = red[0];
#pragma unroll
        for (int i = 1; i < 8; i++) s = fmaxf(s, red[i]);
        if (!(s > 0.f)) s = 1.f;
        sc[row] = s;
        m1s = 127.f / s;
    }
    __syncthreads();
    float m1 = m1s;
    char q1[8], q2[8];
#pragma unroll
    for (int i = 0; i < 8; i++) {
        float t = vals[i] * m1;
        float a1 = rintf(t);
        q1[i] = (char)(int)a1;
        q2[i] = (char)(int)rintf((t - a1) * 254.f);
    }
    *(uint2*)(d1 + (size_t)row * MDIM + tid * 8) = *(uint2*)q1;
    *(uint2*)(d2 + (size_t)row * MDIM + tid * 8) = *(uint2*)q2;
}

/* -------- cache copy + bf16 split of past window ------------------------- */
__global__ void copy_cache_kernel(const float4* __restrict__ pk,
                                  const float4* __restrict__ pv,
                                  float4* __restrict__ nk,
                                  float4* __restrict__ nv) {
    int idx = blockIdx.x * blockDim.x + threadIdx.x;
    int which = idx >> 21;
    int r     = idx & ((1 << 21) - 1);
    int bh    = r >> 12;
    int e     = r & 4095;
    const float4* src = which ? pv : pk;
    float4*       dst = which ? nv : nk;
    float4 v = src[(size_t)bh * 8192 + 4096 + e];
    dst[(size_t)bh * 8192 + e] = v;
    int row = e >> 4, dcol = (e & 15) * 4;
    size_t si = ((size_t)bh * SWIN + row) * HDIM + dcol;
    unsigned short* dh = which ? g_vhi : g_khi;
    unsigned short* dl = which ? g_vlo : g_klo;
    unsigned h01 = pack2(v.x, v.y), h23 = pack2(v.z, v.w);
    *(uint2*)(dh + si) = make_uint2(h01, h23);
    *(uint2*)(dl + si) = make_uint2(pack2lo(v.x, v.y, h01), pack2lo(v.z, v.w, h23));
}

/* ================= int8 Ozaki mma GEMM  C = A @ W^T ======================
   CTA 128x128, K-chunk 32 (one s8 k32 mma span), 8 warps (4x2) each 32x64.
   s8-k32 fragments are byte-identical to f16-k16 -> same ldmatrix scheme.
   smem row = 32 int8 padded to 48B (odd multiple of 16 -> conflict-free). */
#define KC 32
#define NCHUNK (MDIM / KC)             /* 64 */
#define ISTR 48
#define COMP_I8 (128 * ISTR)           /* 6144 */
#define STG_I8  (4 * COMP_I8)          /* 24576: A1,A2,B1,B2 */
#define GSMEM_I8 (3 * STG_I8)          /* 73728 */

__device__ __forceinline__ void stage_i8(unsigned sb, int stage,
        const char* __restrict__ A1, const char* __restrict__ A2,
        const char* __restrict__ B1, const char* __restrict__ B2,
        int m0, int n0, int kb, int tid) {
    unsigned st = sb + stage * STG_I8;
    int r = tid >> 1, half = tid & 1;
    unsigned o = r * ISTR + half * 16;
    size_t ga = (size_t)(m0 + r) * MDIM + kb + half * 16;
    size_t gb = (size_t)(n0 + r) * MDIM + kb + half * 16;
    cpa16(st + o,                A1 + ga);
    cpa16(st + COMP_I8 + o,      A2 + ga);
    cpa16(st + 2 * COMP_I8 + o,  B1 + gb);
    cpa16(st + 3 * COMP_I8 + o,  B2 + gb);
}

/* MODE 0: Q (rope, /8, bf16 split -> g_qhi/qlo)
   MODE 1: K (fp32 -> nk; rope bf16 split -> g_khi/klo rows 256..)
   MODE 2: V (fp32 -> nv; bf16 split -> g_vhi/vlo rows 256..)
   MODE 3: O (fp32 -> out)                                                  */
template <int MODE>
__device__ __forceinline__ void gemm_i8(
        const char* __restrict__ A1, const char* __restrict__ A2,
        const float* __restrict__ sAp,
        const char* __restrict__ B1, const char* __restrict__ B2,
        const float* __restrict__ sBp,
        float* __restrict__ dst) {
    extern __shared__ char sm[];
    unsigned sbase = s2u(sm);
    int tid = threadIdx.x, wid = tid >> 5, lane = tid & 31;
    int m0 = blockIdx.y * 128, n0 = blockIdx.x * 128;
    int warp_m = (wid >> 1) * 32, warp_n = (wid & 1) * 64;

    int c11[2][8][4], c12[2][8][4];
#pragma unroll
    for (int mt = 0; mt < 2; mt++)
#pragma unroll
        for (int nt = 0; nt < 8; nt++)
#pragma unroll
            for (int q = 0; q < 4; q++) { c11[mt][nt][q] = 0; c12[mt][nt][q] = 0; }

    stage_i8(sbase, 0, A1, A2, B1, B2, m0, n0, 0,  tid); cp_commit();
    stage_i8(sbase, 1, A1, A2, B1, B2, m0, n0, KC, tid); cp_commit();

    unsigned aoff = (warp_m + (lane & 15)) * ISTR + ((lane >> 4) << 4);
    unsigned boff = (warp_n + ((lane >> 4) << 3) + (lane & 7)) * ISTR
                  + (((lane >> 3) & 1) << 4) + 2 * COMP_I8;

    for (int ch = 0; ch < NCHUNK; ch++) {
        if (ch + 2 < NCHUNK)
            stage_i8(sbase, (ch + 2) % 3, A1, A2, B1, B2, m0, n0, (ch + 2) * KC, tid);
        cp_commit();
        cp_wait2();
        __syncthreads();

        unsigned st = sbase + (ch % 3) * STG_I8;
        unsigned a1f[2][4], a2f[2][4];
#pragma unroll
        for (int mt = 0; mt < 2; mt++) {
            unsigned a = st + aoff + mt * (16 * ISTR);
            ldmx4(a1f[mt], a);
            ldmx4(a2f[mt], a + COMP_I8);
        }
#pragma unroll
        for (int nb = 0; nb < 4; nb++) {
            unsigned b1[4], b2[4];
            unsigned a = st + boff + nb * (16 * ISTR);
            ldmx4(b1, a);
            ldmx4(b2, a + COMP_I8);
            int n0t = 2 * nb, n1t = 2 * nb + 1;
#pragma unroll
            for (int mt = 0; mt < 2; mt++) {
                mma_s8(c11[mt][n0t], a1f[mt], b1[0], b1[1]);
                mma_s8(c11[mt][n1t], a1f[mt], b1[2], b1[3]);
            }
#pragma unroll
            for (int mt = 0; mt < 2; mt++) {
                mma_s8(c12[mt][n0t], a1f[mt], b2[0], b2[1]);
                mma_s8(c12[mt][n1t], a1f[mt], b2[2], b2[3]);
            }
#pragma unroll
            for (int mt = 0; mt < 2; mt++) {
                mma_s8(c12[mt][n0t], a2f[mt], b1[0], b1[1]);
                mma_s8(c12[mt][n1t], a2f[mt], b1[2], b1[3]);
            }
        }
        __syncthreads();
    }

    /* epilogue: val = sA*sB*(C11/127^2 + C12p21/(127^2*254)) */
    const float k1 = 6.2000124e-5f;      /* 1/16129        */
    const float k2 = 2.4409497e-7f;      /* 1/(16129*254)  */
    int mb = m0 + warp_m + (lane >> 2);
    int nbase = n0 + warp_n + (lane & 3) * 2;
#pragma unroll
    for (int mt = 0; mt < 2; mt++) {
#pragma unroll
        for (int half = 0; half < 2; half++) {
            int m = mb + mt * 16 + half * 8;
            float sa = sAp[m];
#pragma unroll
            for (int nt = 0; nt < 8; nt++) {
                int n = nbase + nt * 8;
                float x = sa * sBp[n] *
                    ((float)c11[mt][nt][half*2]   * k1 + (float)c12[mt][nt][half*2]   * k2);
                float y = sa * sBp[n+1] *
                    ((float)c11[mt][nt][half*2+1] * k1 + (float)c12[mt][nt][half*2+1] * k2);
                if (MODE == 3) {
                    *(float2*)(dst + (size_t)m * MDIM + n) = make_float2(x, y);
                } else {
                    int b = m >> 8, t = m & 255;
                    int h = n >> 6, hd = n & 63;
                    int bh_ = b * NHEAD + h;
                    if (MODE == 2) {
                        *(float2*)(dst + ((size_t)bh_ * SWIN + SEQT + t) * HDIM + hd)
                            = make_float2(x, y);
                        size_t si = ((size_t)bh_ * SWIN + SEQT + t) * HDIM + hd;
                        unsigned hp = pack2(x, y);
                        *(unsigned*)(g_vhi + si) = hp;
                        *(unsigned*)(g_vlo + si) = pack2lo(x, y, hp);
                    } else {
                        int p = hd >> 1;
                        float cth = g_cos[t * 32 + p], sth = g_sin[t * 32 + p];
                        float rx = x * cth - y * sth;
                        float ry = x * sth + y * cth;
                        if (MODE == 0) {
                            size_t si = ((size_t)bh_ * SEQT + t) * HDIM + hd;
                            float qx = rx * 0.125f, qy = ry * 0.125f;
                            unsigned hp = pack2(qx, qy);
                            *(unsigned*)(g_qhi + si) = hp;
                            *(unsigned*)(g_qlo + si) = pack2lo(qx, qy, hp);
                        } else {
                            *(float2*)(dst + ((size_t)bh_ * SWIN + SEQT + t) * HDIM + hd)
                                = make_float2(x, y);
                            size_t si = ((size_t)bh_ * SWIN + SEQT + t) * HDIM + hd;
                            unsigned hp = pack2(rx, ry);
                            *(unsigned*)(g_khi + si) = hp;
                            *(unsigned*)(g_klo + si) = pack2lo(rx, ry, hp);
                        }
                    }
                }
            }
        }
    }
}

__global__ void __launch_bounds__(256, 1)
gemm_qkv_i8(float* __restrict__ nk, float* __restrict__ nv) {
    if      (blockIdx.z == 0)
        gemm_i8<0>(g_x1, g_x2, g_sx, g_w1,          g_w2,          g_sw,          nullptr);
    else if (blockIdx.z == 1)
        gemm_i8<1>(g_x1, g_x2, g_sx, g_w1 + 1u*WN,  g_w2 + 1u*WN,  g_sw + MDIM,   nk);
    else
        gemm_i8<2>(g_x1, g_x2, g_sx, g_w1 + 2u*WN,  g_w2 + 2u*WN,  g_sw + 2*MDIM, nv);
}

__global__ void __launch_bounds__(256, 1)
gemm_o_i8(float* __restrict__ out) {
    gemm_i8<3>(g_a1, g_a2, g_sa, g_w1 + 3u*WN, g_w2 + 3u*WN, g_sw + 3*MDIM, out);
}

/* ============== flash attention on mma.sync (3-term bf16 split) ========== */
#define AST   144
#define ATILE (64 * AST)
#define ASM_ST (2 * ATILE)
#define ATT_SMEM (ASM_ST + 8 * ATILE)  /* 92160 */

__device__ __forceinline__ void attn_stage(unsigned sb, int s, int bh, int kt, int tid) {
    unsigned st = sb + ASM_ST + s * (4 * ATILE);
#pragma unroll
    for (int i = 0; i < 4; i++) {
        int op = tid + i * 128;
        int r = op >> 3, seg = op & 7;
        size_t src = ((size_t)bh * SWIN + kt * 64 + r) * HDIM + seg * 8;
        unsigned d = st + r * AST + seg * 16;
        cpa16(d,             g_khi + src);
        cpa16(d + ATILE,     g_klo + src);
        cpa16(d + 2 * ATILE, g_vhi + src);
        cpa16(d + 3 * ATILE, g_vlo + src);
    }
}

__global__ void __launch_bounds__(128, 2) attn_kernel() {
    extern __shared__ char sm[];
    unsigned sb = s2u(sm);
    int qt = blockIdx.x, bh = blockIdx.y;
    int tid = threadIdx.x, w = tid >> 5, lane = tid & 31;

#pragma unroll
    for (int i = 0; i < 4; i++) {
        int op = tid + i * 128;
        int r = op >> 3, seg = op & 7;
        size_t src = ((size_t)bh * SEQT + qt * 64 + r) * HDIM + seg * 8;
        unsigned d = sb + r * AST + seg * 16;
        cpa16(d,         g_qhi + src);
        cpa16(d + ATILE, g_qlo + src);
    }
    attn_stage(sb, 0, bh, 0, tid);
    cp_commit();
    attn_stage(sb, 1, bh, 1, tid);
    cp_commit();
    cp_wait1();
    __syncthreads();

    unsigned aqh[4][4], aql[4][4];
    unsigned aoff = (w * 16 + (lane & 15)) * AST + ((lane >> 4) << 4);
#pragma unroll
    for (int ks = 0; ks < 4; ks++) {
        ldmx4(aqh[ks], sb + aoff + ks * 32);
        ldmx4(aql[ks], sb + ATILE + aoff + ks * 32);
    }

    unsigned boffK = ((((lane >> 4) << 3) + (lane & 7))) * AST + (((lane >> 3) & 1) << 4);
    unsigned voff  = ((lane & 7) + (((lane >> 3) & 1) << 3)) * AST + ((lane >> 4) << 4);

    float acc[8][4];
#pragma unroll
    for (int dt = 0; dt < 8; dt++)
#pragma unroll
        for (int q = 0; q < 4; q++) acc[dt][q] = 0.f;
    float mrow[2] = {-1e30f, -1e30f}, lrow[2] = {0.f, 0.f};

    int ktmax = qt + 4;
    for (int kt = 0; kt <= ktmax; kt++) {
        int cur = kt & 1;
        cp_wait1();
        __syncthreads();
        unsigned stK = sb + ASM_ST + cur * (4 * ATILE);
        unsigned stV = stK + 2 * ATILE;

        float sc[8][4];
#pragma unroll
        for (int j = 0; j < 8; j++)
#pragma unroll
            for (int q = 0; q < 4; q++) sc[j][q] = 0.f;
#pragma unroll
        for (int ks = 0; ks < 4; ks++) {
#pragma unroll
            for (int np = 0; np < 4; np++) {
                unsigned kh[4], kl[4];
                unsigned a = stK + boffK + np * (16 * AST) + ks * 32;
                ldmx4(kh, a);
                ldmx4(kl, a + ATILE);
                mma_bf16(sc[2*np],   aqh[ks], kh[0], kh[1]);
                mma_bf16(sc[2*np+1], aqh[ks], kh[2], kh[3]);
                mma_bf16(sc[2*np],   aqh[ks], kl[0], kl[1]);
                mma_bf16(sc[2*np+1], aqh[ks], kl[2], kl[3]);
                mma_bf16(sc[2*np],   aql[ks], kh[0], kh[1]);
                mma_bf16(sc[2*np+1], aql[ks], kh[2], kh[3]);
            }
        }
        if (kt == ktmax) {
#pragma unroll
            for (int j = 0; j < 8; j++)
#pragma unroll
                for (int q = 0; q < 4; q++) {
                    int col = j * 8 + (lane & 3) * 2 + (q & 1);
                    int row = w * 16 + (lane >> 2) + (q >> 1) * 8;
                    if (col > row) sc[j][q] = -1e30f;
                }
        }
#pragma unroll
        for (int h = 0; h < 2; h++) {
            float mx = -1e30f;
#pragma unroll
            for (int j = 0; j < 8; j++)
                mx = fmaxf(mx, fmaxf(sc[j][2*h], sc[j][2*h+1]));
            mx = fmaxf(mx, __shfl_xor_sync(0xffffffffu, mx, 1));
            mx = fmaxf(mx, __shfl_xor_sync(0xffffffffu, mx, 2));
            float mnew = fmaxf(mrow[h], mx);
            float fct  = __expf(mrow[h] - mnew);
            mrow[h] = mnew;
            float sum = 0.f;
#pragma unroll
            for (int j = 0; j < 8; j++) {
                float p0 = __expf(sc[j][2*h]   - mnew);
                float p1 = __expf(sc[j][2*h+1] - mnew);
                sc[j][2*h] = p0; sc[j][2*h+1] = p1;
                sum += p0 + p1;
            }
            sum += __shfl_xor_sync(0xffffffffu, sum, 1);
            sum += __shfl_xor_sync(0xffffffffu, sum, 2);
            lrow[h] = lrow[h] * fct + sum;
#pragma unroll
            for (int dt = 0; dt < 8; dt++) {
                acc[dt][2*h]   *= fct;
                acc[dt][2*h+1] *= fct;
            }
        }
#pragma unroll
        for (int kp = 0; kp < 4; kp++) {
            unsigned aph[4], apl[4];
            aph[0] = pack2(sc[2*kp][0],   sc[2*kp][1]);
            aph[1] = pack2(sc[2*kp][2],   sc[2*kp][3]);
            aph[2] = pack2(sc[2*kp+1][0], sc[2*kp+1][1]);
            aph[3] = pack2(sc[2*kp+1][2], sc[2*kp+1][3]);
            apl[0] = pack2lo(sc[2*kp][0],   sc[2*kp][1],   aph[0]);
            apl[1] = pack2lo(sc[2*kp][2],   sc[2*kp][3],   aph[1]);
            apl[2] = pack2lo(sc[2*kp+1][0], sc[2*kp+1][1], aph[2]);
            apl[3] = pack2lo(sc[2*kp+1][2], sc[2*kp+1][3], aph[3]);
#pragma unroll
            for (int dd = 0; dd < 4; dd++) {
                unsigned vh[4], vl[4];
                unsigned a = stV + voff + kp * (16 * AST) + dd * 32;
                ldmx4t(vh, a);
                ldmx4t(vl, a + ATILE);
                mma_bf16(acc[2*dd],   aph, vh[0], vh[1]);
                mma_bf16(acc[2*dd+1], aph, vh[2], vh[3]);
                mma_bf16(acc[2*dd],   aph, vl[0], vl[1]);
                mma_bf16(acc[2*dd+1], aph, vl[2], vl[3]);
                mma_bf16(acc[2*dd],   apl, vh[0], vh[1]);
                mma_bf16(acc[2*dd+1], apl, vh[2], vh[3]);
            }
        }
        __syncthreads();
        if (kt + 2 <= ktmax) attn_stage(sb, cur, bh, kt + 2, tid);
        cp_commit();
    }

    /* epilogue: normalize -> fp32 g_attn (re-quantized before O GEMM) */
    int b = bh >> 5, hh = bh & 31;
#pragma unroll
    for (int h = 0; h < 2; h++) {
        int t = qt * 64 + w * 16 + (lane >> 2) + h * 8;
        float inv = 1.f / lrow[h];
#pragma unroll
        for (int dt = 0; dt < 8; dt++) {
            float o0 = acc[dt][2*h] * inv, o1 = acc[dt][2*h+1] * inv;
            size_t idx = ((size_t)(b * SEQT + t)) * MDIM + hh * HDIM
                       + dt * 8 + (lane & 3) * 2;
            *(float2*)(g_attn + idx) = make_float2(o0, o1);
        }
    }
}

/* ---------------- launch -------------------------------------------------- */
extern "C" void kernel_launch(void* const* d_in, const int* in_sizes, int n_in,
                              void* d_out, int out_size) {
    (void)in_sizes; (void)n_in; (void)out_size;
    const float* x  = (const float*)d_in[0];
    const float* pk = (const float*)d_in[1];
    const float* pv = (const float*)d_in[2];
    const float* Wq = (const float*)d_in[3];
    const float* Wk = (const float*)d_in[4];
    const float* Wv = (const float*)d_in[5];
    const float* Wo = (const float*)d_in[6];
    const int*  pos = (const int*)d_in[7];

    float* out = (float*)d_out;
    float* nk  = out + (size_t)MROWS * MDIM;
    float* nv  = nk + (size_t)BATCH * NHEAD * SWIN * HDIM;

    char *gx1, *gx2, *gw1, *gw2, *ga1, *ga2;
    float *gsx, *gsw, *gsa, *gattn;
    cudaGetSymbolAddress((void**)&gx1, g_x1);
    cudaGetSymbolAddress((void**)&gx2, g_x2);
    cudaGetSymbolAddress((void**)&gw1, g_w1);
    cudaGetSymbolAddress((void**)&gw2, g_w2);
    cudaGetSymbolAddress((void**)&ga1, g_a1);
    cudaGetSymbolAddress((void**)&ga2, g_a2);
    cudaGetSymbolAddress((void**)&gsx, g_sx);
    cudaGetSymbolAddress((void**)&gsw, g_sw);
    cudaGetSymbolAddress((void**)&gsa, g_sa);
    cudaGetSymbolAddress((void**)&gattn, g_attn);

    cudaFuncSetAttribute(attn_kernel,
                         cudaFuncAttributeMaxDynamicSharedMemorySize, ATT_SMEM);
    cudaFuncSetAttribute(gemm_qkv_i8,
                         cudaFuncAttributeMaxDynamicSharedMemorySize, GSMEM_I8);
    cudaFuncSetAttribute(gemm_o_i8,
                         cudaFuncAttributeMaxDynamicSharedMemorySize, GSMEM_I8);

    rope_table_kernel<<<32, 256>>>(pos);
    quantize_kernel<<<MROWS, 256>>>(x,  gx1, gx2, gsx);
    quantize_kernel<<<MDIM, 256>>>(Wq, gw1,                 gw2,                 gsw);
    quantize_kernel<<<MDIM, 256>>>(Wk, gw1 + (size_t)WN,    gw2 + (size_t)WN,    gsw + MDIM);
    quantize_kernel<<<MDIM, 256>>>(Wv, gw1 + 2*(size_t)WN,  gw2 + 2*(size_t)WN,  gsw + 2*MDIM);
    quantize_kernel<<<MDIM, 256>>>(Wo, gw1 + 3*(size_t)WN,  gw2 + 3*(size_t)WN,  gsw + 3*MDIM);
    copy_cache_kernel<<<(2 * (1 << 21)) / 256, 256>>>(
        (const float4*)pk, (const float4*)pv, (float4*)nk, (float4*)nv);
    gemm_qkv_i8<<<dim3(MDIM / 128, MROWS / 128, 3), 256, GSMEM_I8>>>(nk, nv);
    attn_kernel<<<dim3(4, BATCH * NHEAD), 128, ATT_SMEM>>>();
    quantize_kernel<<<MROWS, 256>>>(gattn, ga1, ga2, gsa);
    gemm_o_i8<<<dim3(MDIM / 128, MROWS / 128, 1), 256, GSMEM_I8>>>(out);
}